// round 14
// baseline (speedup 1.0000x reference)
#include <cuda_runtime.h>
#include <cuda_bf16.h>
#include <cuda_fp16.h>
#include <stdint.h>
#include <math.h>

// Problem constants
#define BSZ 2
#define SEQ 2048
#define DM  1024
#define DFF 4096
#define NH  16
#define DKV 64
#define MTOT (BSZ*SEQ)   // 4096

// ---------------------------------------------------------------------------
// Scratch buffers
// ---------------------------------------------------------------------------
__device__ __align__(256) float g_x  [MTOT*DM];
__device__ __align__(256) float g_t  [MTOT*DM];

__device__ __align__(256) __nv_bfloat16 g_aHi[MTOT*DM];
__device__ __align__(256) __half g_xHi[MTOT*DM];
__device__ __align__(256) __half g_hHi[(size_t)MTOT*DFF];
__device__ __align__(256) __nv_bfloat16 g_qHi[MTOT*DM];
__device__ __align__(256) __nv_bfloat16 g_kHi[MTOT*DM];
__device__ __align__(256) __nv_bfloat16 g_vHi[MTOT*DM];
__device__ __align__(256) __nv_bfloat16 g_ctxHi[MTOT*DM];
__device__ __align__(256) __nv_bfloat16 g_wqkvT[3*DM*DM];
__device__ __align__(256) __nv_bfloat16 g_woT[DM*DM];
__device__ __align__(256) __half g_w1T[(size_t)DFF*DM];
__device__ __align__(256) __half g_w2T[(size_t)DM*DFF];

// ---------------------------------------------------------------------------
// PTX helpers
// ---------------------------------------------------------------------------
static __device__ __forceinline__ uint32_t smem_u32(const void* p) {
    uint32_t a;
    asm("{ .reg .u64 t; cvta.to.shared.u64 t, %1; cvt.u32.u64 %0, t; }"
        : "=r"(a) : "l"(p));
    return a;
}
static __device__ __forceinline__ void cp16(uint32_t dst, const void* src) {
    asm volatile("cp.async.cg.shared.global [%0], [%1], 16;" :: "r"(dst), "l"(src));
}
static __device__ __forceinline__ uint32_t swz(uint32_t off) {
    return off ^ ((off >> 3) & 0x70);
}
static __device__ __forceinline__ void ldsm4(uint32_t* r, uint32_t addr) {
    asm volatile("ldmatrix.sync.aligned.m8n8.x4.shared.b16 {%0,%1,%2,%3}, [%4];"
        : "=r"(r[0]), "=r"(r[1]), "=r"(r[2]), "=r"(r[3]) : "r"(addr));
}
static __device__ __forceinline__ void ldsm4t(uint32_t* r, uint32_t addr) {
    asm volatile("ldmatrix.sync.aligned.m8n8.x4.trans.shared.b16 {%0,%1,%2,%3}, [%4];"
        : "=r"(r[0]), "=r"(r[1]), "=r"(r[2]), "=r"(r[3]) : "r"(addr));
}
static __device__ __forceinline__ void hmma(float* d, const uint32_t* a,
                                            const uint32_t* b) {
    asm volatile(
        "mma.sync.aligned.m16n8k16.row.col.f32.bf16.bf16.f32 "
        "{%0,%1,%2,%3}, {%4,%5,%6,%7}, {%8,%9}, {%0,%1,%2,%3};"
        : "+f"(d[0]), "+f"(d[1]), "+f"(d[2]), "+f"(d[3])
        : "r"(a[0]), "r"(a[1]), "r"(a[2]), "r"(a[3]), "r"(b[0]), "r"(b[1]));
}
static __device__ __forceinline__ void hmmah(float* d, const uint32_t* a,
                                             const uint32_t* b) {
    asm volatile(
        "mma.sync.aligned.m16n8k16.row.col.f32.f16.f16.f32 "
        "{%0,%1,%2,%3}, {%4,%5,%6,%7}, {%8,%9}, {%0,%1,%2,%3};"
        : "+f"(d[0]), "+f"(d[1]), "+f"(d[2]), "+f"(d[3])
        : "r"(a[0]), "r"(a[1]), "r"(a[2]), "r"(a[3]), "r"(b[0]), "r"(b[1]));
}
static __device__ __forceinline__ uint32_t packbf2(float x, float y) {
    __nv_bfloat162 t = __floats2bfloat162_rn(x, y);
    return *reinterpret_cast<uint32_t*>(&t);
}
static __device__ __forceinline__ uint32_t packh2(float x, float y) {
    __half2 t = __floats2half2_rn(x, y);
    return *reinterpret_cast<uint32_t*>(&t);
}

// ===========================================================================
// 1-TERM GEMM, 4-warp CTA, 128x128 tile, warp 64x64, register-level
// fragment double-buffering across ks-steps (LDSM hides under HMMA).
// 64 KB smem, ~220 regs -> 2 CTAs/SM.
// bf16 variant (QKV/Wo): MODE 0 QKV epilogue, MODE 1 fp32+residual.
// ===========================================================================
#define G1_STAGE (32*1024)
#define G1_OFF_B (16*1024)
#define GEMM1_SMEM (2*G1_STAGE)   // 64 KB

static __device__ __forceinline__ void load_tile1(
    uint32_t sb, int stage, int it,
    const __nv_bfloat16* __restrict__ A, const __nv_bfloat16* __restrict__ B,
    int mBase, int nBase, int K, int tid)
{
    const uint32_t base = sb + stage * G1_STAGE;
    const int k0 = it * 64;
    #pragma unroll
    for (int i = 0; i < 8; i++) {
        int c = tid + i * 128;
        int row = c >> 3, chk = c & 7;
        cp16(base + swz(row * 128 + chk * 16),
             A + (size_t)(mBase + row) * K + k0 + chk * 8);
    }
    #pragma unroll
    for (int i = 0; i < 8; i++) {
        int c = tid + i * 128;
        int row = c >> 3, chk = c & 7;
        cp16(base + G1_OFF_B + swz(row * 128 + chk * 16),
             B + (size_t)(nBase + row) * K + k0 + chk * 8);
    }
    asm volatile("cp.async.commit_group;" ::: "memory");
}

template<int MODE>
__global__ void __launch_bounds__(128, 2) gemm1(
    const __nv_bfloat16* __restrict__ A, const __nv_bfloat16* __restrict__ B,
    const float* __restrict__ b0, const float* __restrict__ b1,
    const float* __restrict__ b2, const float* __restrict__ res,
    float* __restrict__ o0, int K, int ldc)
{
    extern __shared__ char smem[];
    const uint32_t sb = smem_u32(smem);
    const int tid  = threadIdx.x;
    const int wid  = tid >> 5;
    const int lane = tid & 31;
    const int warpM = wid >> 1;
    const int warpN = wid & 1;
    const int mBase = blockIdx.y * 128;
    const int nBase = blockIdx.x * 128;

    float acc[4][8][4];
    #pragma unroll
    for (int i = 0; i < 4; i++)
        #pragma unroll
        for (int j = 0; j < 8; j++)
            #pragma unroll
            for (int e = 0; e < 4; e++) acc[i][j][e] = 0.f;

    const int T = K / 64;
    load_tile1(sb, 0, 0, A, B, mBase, nBase, K, tid);

    const int aRow  = warpM * 64 + ((lane >> 3) & 1) * 8 + (lane & 7);
    const int aKsel = (lane >> 4) * 16;
    const int bRow  = warpN * 64 + (lane >> 4) * 8 + (lane & 7);
    const int bKsel = ((lane >> 3) & 1) * 16;

    for (int it = 0; it < T; it++) {
        const int s = it & 1;
        if (it + 1 < T) {
            load_tile1(sb, s ^ 1, it + 1, A, B, mBase, nBase, K, tid);
            asm volatile("cp.async.wait_group 1;" ::: "memory");
        } else {
            asm volatile("cp.async.wait_group 0;" ::: "memory");
        }
        __syncthreads();

        const uint32_t st = sb + s * G1_STAGE;
        uint32_t a[2][4][4], b[2][4][4];
        // prefetch ks=0 fragments
        #pragma unroll
        for (int ma = 0; ma < 4; ma++)
            ldsm4(a[0][ma], st + swz((uint32_t)(aRow + ma * 16) * 128 + aKsel));
        #pragma unroll
        for (int np = 0; np < 4; np++)
            ldsm4(b[0][np], st + G1_OFF_B +
                  swz((uint32_t)(bRow + np * 16) * 128 + bKsel));
        #pragma unroll
        for (int ks = 0; ks < 4; ks++) {
            const int cur = ks & 1, nxt = cur ^ 1;
            if (ks < 3) {           // prefetch next ks while HMMAs run
                const int kb = (ks + 1) * 32;
                #pragma unroll
                for (int ma = 0; ma < 4; ma++)
                    ldsm4(a[nxt][ma],
                          st + swz((uint32_t)(aRow + ma * 16) * 128 + kb + aKsel));
                #pragma unroll
                for (int np = 0; np < 4; np++)
                    ldsm4(b[nxt][np], st + G1_OFF_B +
                          swz((uint32_t)(bRow + np * 16) * 128 + kb + bKsel));
            }
            #pragma unroll
            for (int ma = 0; ma < 4; ma++)
                #pragma unroll
                for (int na = 0; na < 8; na++)
                    hmma(acc[ma][na], a[cur][ma], &b[cur][na >> 1][(na & 1) * 2]);
        }
        __syncthreads();
    }

    const int gr = lane >> 2;
    const int gc = (lane & 3) * 2;
    #pragma unroll
    for (int ma = 0; ma < 4; ma++) {
        #pragma unroll
        for (int na = 0; na < 8; na++) {
            const int row0 = mBase + warpM * 64 + ma * 16 + gr;
            const int colg = nBase + warpN * 64 + na * 8 + gc;
            float d0 = acc[ma][na][0], d1 = acc[ma][na][1];
            float d2 = acc[ma][na][2], d3 = acc[ma][na][3];
            if (MODE == 0) {    // QKV
                const int seg = colg >> 10;
                const int col = colg & 1023;
                const float* bb = (seg == 0) ? b0 : ((seg == 1) ? b1 : b2);
                __nv_bfloat16* Hi = (seg == 0) ? g_qHi : ((seg == 1) ? g_kHi : g_vHi);
                const float sc = (seg == 0) ? 0.125f : 1.0f;
                float bv0 = bb[col], bv1 = bb[col + 1];
                size_t gi0 = (size_t)row0 * 1024 + col;
                size_t gi1 = (size_t)(row0 + 8) * 1024 + col;
                *(uint32_t*)(Hi + gi0) = packbf2((d0 + bv0) * sc, (d1 + bv1) * sc);
                *(uint32_t*)(Hi + gi1) = packbf2((d2 + bv0) * sc, (d3 + bv1) * sc);
            } else {            // fp32 + residual
                float bv0 = b0[colg], bv1 = b0[colg + 1];
                size_t gi0 = (size_t)row0 * ldc + colg;
                size_t gi1 = (size_t)(row0 + 8) * ldc + colg;
                float2 r0 = *(const float2*)(res + gi0);
                float2 r1 = *(const float2*)(res + gi1);
                *(float2*)(o0 + gi0) = make_float2(d0 + bv0 + r0.x, d1 + bv1 + r0.y);
                *(float2*)(o0 + gi1) = make_float2(d2 + bv0 + r1.x, d3 + bv1 + r1.y);
            }
        }
    }
}

// ===========================================================================
// fp16 variant (FFN), same structure + fragment double-buffering.
// MODE 1: fp32 out + residual   MODE 2: relu + fp16 out
// ===========================================================================
static __device__ __forceinline__ void load_tileh(
    uint32_t sb, int stage, int it,
    const __half* __restrict__ A, const __half* __restrict__ B,
    int mBase, int nBase, int K, int tid)
{
    const uint32_t base = sb + stage * G1_STAGE;
    const int k0 = it * 64;
    #pragma unroll
    for (int i = 0; i < 8; i++) {
        int c = tid + i * 128;
        int row = c >> 3, chk = c & 7;
        cp16(base + swz(row * 128 + chk * 16),
             A + (size_t)(mBase + row) * K + k0 + chk * 8);
    }
    #pragma unroll
    for (int i = 0; i < 8; i++) {
        int c = tid + i * 128;
        int row = c >> 3, chk = c & 7;
        cp16(base + G1_OFF_B + swz(row * 128 + chk * 16),
             B + (size_t)(nBase + row) * K + k0 + chk * 8);
    }
    asm volatile("cp.async.commit_group;" ::: "memory");
}

template<int MODE>
__global__ void __launch_bounds__(128, 2) gemmh(
    const __half* __restrict__ A, const __half* __restrict__ B,
    const float* __restrict__ b0, const float* __restrict__ res,
    float* __restrict__ o0, __half* __restrict__ oH,
    int K, int ldc)
{
    extern __shared__ char smem[];
    const uint32_t sb = smem_u32(smem);
    const int tid  = threadIdx.x;
    const int wid  = tid >> 5;
    const int lane = tid & 31;
    const int warpM = wid >> 1;
    const int warpN = wid & 1;
    const int mBase = blockIdx.y * 128;
    const int nBase = blockIdx.x * 128;

    float acc[4][8][4];
    #pragma unroll
    for (int i = 0; i < 4; i++)
        #pragma unroll
        for (int j = 0; j < 8; j++)
            #pragma unroll
            for (int e = 0; e < 4; e++) acc[i][j][e] = 0.f;

    const int T = K / 64;
    load_tileh(sb, 0, 0, A, B, mBase, nBase, K, tid);

    const int aRow  = warpM * 64 + ((lane >> 3) & 1) * 8 + (lane & 7);
    const int aKsel = (lane >> 4) * 16;
    const int bRow  = warpN * 64 + (lane >> 4) * 8 + (lane & 7);
    const int bKsel = ((lane >> 3) & 1) * 16;

    for (int it = 0; it < T; it++) {
        const int s = it & 1;
        if (it + 1 < T) {
            load_tileh(sb, s ^ 1, it + 1, A, B, mBase, nBase, K, tid);
            asm volatile("cp.async.wait_group 1;" ::: "memory");
        } else {
            asm volatile("cp.async.wait_group 0;" ::: "memory");
        }
        __syncthreads();

        const uint32_t st = sb + s * G1_STAGE;
        uint32_t a[2][4][4], b[2][4][4];
        #pragma unroll
        for (int ma = 0; ma < 4; ma++)
            ldsm4(a[0][ma], st + swz((uint32_t)(aRow + ma * 16) * 128 + aKsel));
        #pragma unroll
        for (int np = 0; np < 4; np++)
            ldsm4(b[0][np], st + G1_OFF_B +
                  swz((uint32_t)(bRow + np * 16) * 128 + bKsel));
        #pragma unroll
        for (int ks = 0; ks < 4; ks++) {
            const int cur = ks & 1, nxt = cur ^ 1;
            if (ks < 3) {
                const int kb = (ks + 1) * 32;
                #pragma unroll
                for (int ma = 0; ma < 4; ma++)
                    ldsm4(a[nxt][ma],
                          st + swz((uint32_t)(aRow + ma * 16) * 128 + kb + aKsel));
                #pragma unroll
                for (int np = 0; np < 4; np++)
                    ldsm4(b[nxt][np], st + G1_OFF_B +
                          swz((uint32_t)(bRow + np * 16) * 128 + kb + bKsel));
            }
            #pragma unroll
            for (int ma = 0; ma < 4; ma++)
                #pragma unroll
                for (int na = 0; na < 8; na++)
                    hmmah(acc[ma][na], a[cur][ma], &b[cur][na >> 1][(na & 1) * 2]);
        }
        __syncthreads();
    }

    const int gr = lane >> 2;
    const int gc = (lane & 3) * 2;
    #pragma unroll
    for (int ma = 0; ma < 4; ma++) {
        #pragma unroll
        for (int na = 0; na < 8; na++) {
            const int row0 = mBase + warpM * 64 + ma * 16 + gr;
            const int colg = nBase + warpN * 64 + na * 8 + gc;
            float d0 = acc[ma][na][0], d1 = acc[ma][na][1];
            float d2 = acc[ma][na][2], d3 = acc[ma][na][3];
            float bv0 = b0[colg], bv1 = b0[colg + 1];
            size_t gi0 = (size_t)row0 * ldc + colg;
            size_t gi1 = (size_t)(row0 + 8) * ldc + colg;
            if (MODE == 1) {
                float2 r0 = *(const float2*)(res + gi0);
                float2 r1 = *(const float2*)(res + gi1);
                *(float2*)(o0 + gi0) = make_float2(d0 + bv0 + r0.x, d1 + bv1 + r0.y);
                *(float2*)(o0 + gi1) = make_float2(d2 + bv0 + r1.x, d3 + bv1 + r1.y);
            } else {
                *(uint32_t*)(oH + gi0) = packh2(fmaxf(d0 + bv0, 0.f),
                                                fmaxf(d1 + bv1, 0.f));
                *(uint32_t*)(oH + gi1) = packh2(fmaxf(d2 + bv0, 0.f),
                                                fmaxf(d3 + bv1, 0.f));
            }
        }
    }
}

// ---------------------------------------------------------------------------
// Flash attention (unchanged from R13)
// ---------------------------------------------------------------------------
#define AQ_HI 0
#define AKV   (16*1024)
#define AKV_STAGE (32*1024)
#define ATT_SMEM (AKV + 2*AKV_STAGE)   // 80 KB

__global__ void __launch_bounds__(256, 2) attn_mma(
    const __nv_bfloat16* __restrict__ Qhi,
    const __nv_bfloat16* __restrict__ Khi,
    const __nv_bfloat16* __restrict__ Vhi,
    __nv_bfloat16* __restrict__ ctxHi)
{
    extern __shared__ char smem[];
    const uint32_t sb = smem_u32(smem);
    const int tid  = threadIdx.x;
    const int wid  = tid >> 5;
    const int lane = tid & 31;
    const int bh = blockIdx.y;
    const size_t base  = (size_t)bh * (SEQ * DKV);
    const size_t qbase = base + (size_t)blockIdx.x * 128 * DKV;

    #pragma unroll
    for (int i = 0; i < 4; i++) {
        int c = tid + i * 256;
        int row = c >> 3, chk = c & 7;
        cp16(sb + AQ_HI + swz(row * 128 + chk * 16),
             Qhi + qbase + (size_t)row * 64 + chk * 8);
    }
    auto load_kv = [&](int stage, int it) {
        const uint32_t dstb = sb + AKV + stage * AKV_STAGE;
        const int kt = it * 128;
        #pragma unroll
        for (int i = 0; i < 8; i++) {
            int c = tid + i * 256;
            int buf = c >> 10;
            int idx = c & 1023;
            int row = idx >> 3, chk = idx & 7;
            const __nv_bfloat16* src = buf ? Vhi : Khi;
            cp16(dstb + buf * 16384 + swz(row * 128 + chk * 16),
                 src + base + (size_t)(kt + row) * 64 + chk * 8);
        }
        asm volatile("cp.async.commit_group;" ::: "memory");
    };
    load_kv(0, 0);

    float rsum0 = 0.f, rsum1 = 0.f;
    float o[8][4];
    #pragma unroll
    for (int n = 0; n < 8; n++)
        #pragma unroll
        for (int e = 0; e < 4; e++) o[n][e] = 0.f;

    const int aRow  = wid * 16 + ((lane >> 3) & 1) * 8 + (lane & 7);
    const int aKsel = (lane >> 4) * 16;
    const int bR    = (lane >> 4) * 8 + (lane & 7);
    const int bKsel = ((lane >> 3) & 1) * 16;
    const int vRowL = ((lane >> 3) & 1) * 8 + (lane & 7);
    const int vDL   = (lane >> 4) * 16;

    const int T = SEQ / 128;   // 16
    for (int it = 0; it < T; it++) {
        const int s = it & 1;
        if (it + 1 < T) {
            load_kv(s ^ 1, it + 1);
            asm volatile("cp.async.wait_group 1;" ::: "memory");
        } else {
            asm volatile("cp.async.wait_group 0;" ::: "memory");
        }
        __syncthreads();
        const uint32_t st = sb + AKV + s * AKV_STAGE;

        #pragma unroll
        for (int half = 0; half < 2; half++) {
            const uint32_t kOff = st + half * 8192;
            const uint32_t vOff = st + 16384 + half * 8192;

            float sacc[8][4];
            #pragma unroll
            for (int n = 0; n < 8; n++)
                #pragma unroll
                for (int e = 0; e < 4; e++) sacc[n][e] = 0.f;

            #pragma unroll
            for (int ks = 0; ks < 4; ks++) {
                const int kbyte = ks * 32;
                uint32_t qh[4];
                ldsm4(qh, sb + AQ_HI + swz((uint32_t)aRow * 128 + kbyte + aKsel));
                uint32_t kh[4][4];
                #pragma unroll
                for (int nb = 0; nb < 4; nb++)
                    ldsm4(kh[nb], kOff +
                          swz((uint32_t)(nb * 16 + bR) * 128 + kbyte + bKsel));
                #pragma unroll
                for (int nt = 0; nt < 8; nt++)
                    hmma(sacc[nt], qh, &kh[nt >> 1][(nt & 1) * 2]);
            }

            #pragma unroll
            for (int j = 0; j < 4; j++) {
                float* s0 = sacc[2*j];
                float* s1 = sacc[2*j + 1];
                float p00 = __expf(s0[0]), p01 = __expf(s0[1]);
                float p02 = __expf(s0[2]), p03 = __expf(s0[3]);
                float p10 = __expf(s1[0]), p11 = __expf(s1[1]);
                float p12 = __expf(s1[2]), p13 = __expf(s1[3]);
                rsum0 += p00 + p01 + p10 + p11;
                rsum1 += p02 + p03 + p12 + p13;
                uint32_t ph[4];
                ph[0] = packbf2(p00, p01);
                ph[1] = packbf2(p02, p03);
                ph[2] = packbf2(p10, p11);
                ph[3] = packbf2(p12, p13);
                uint32_t vh[4][4];
                #pragma unroll
                for (int dblk = 0; dblk < 4; dblk++)
                    ldsm4t(vh[dblk], vOff +
                           swz((uint32_t)(j * 16 + vRowL) * 128 +
                               dblk * 32 + vDL));
                #pragma unroll
                for (int dt = 0; dt < 8; dt++)
                    hmma(o[dt], ph, &vh[dt >> 1][(dt & 1) * 2]);
            }
        }
        __syncthreads();
    }

    rsum0 += __shfl_xor_sync(0xffffffffu, rsum0, 1);
    rsum0 += __shfl_xor_sync(0xffffffffu, rsum0, 2);
    rsum1 += __shfl_xor_sync(0xffffffffu, rsum1, 1);
    rsum1 += __shfl_xor_sync(0xffffffffu, rsum1, 2);

    const int b = bh >> 4, h = bh & 15;
    const float inv0 = 1.f / rsum0;
    const float inv1 = 1.f / rsum1;
    const int s2 = blockIdx.x * 128 + wid * 16 + (lane >> 2);
    #pragma unroll
    for (int nt = 0; nt < 8; nt++) {
        const int d0 = h * 64 + nt * 8 + (lane & 3) * 2;
        size_t gi0 = ((size_t)(b * SEQ + s2))     * DM + d0;
        size_t gi1 = ((size_t)(b * SEQ + s2 + 8)) * DM + d0;
        *(uint32_t*)(ctxHi + gi0) = packbf2(o[nt][0] * inv0, o[nt][1] * inv0);
        *(uint32_t*)(ctxHi + gi1) = packbf2(o[nt][2] * inv1, o[nt][3] * inv1);
    }
}

// ---------------------------------------------------------------------------
// Merged preprocessing: weight transposes + data fp32->bf16 convert
// ---------------------------------------------------------------------------
__global__ void __launch_bounds__(256) transpose_all(
    const float* __restrict__ wq, const float* __restrict__ wk,
    const float* __restrict__ wv, const float* __restrict__ wo,
    const float* __restrict__ w1, const float* __restrict__ w2,
    const float* __restrict__ data)
{
    __shared__ float t[32][33];
    const int b = blockIdx.x;
    if (b >= 12288) {
        int i = (b - 12288) * 256 + threadIdx.x;
        float4 v = ((const float4*)data)[i];
        __nv_bfloat162* H = (__nv_bfloat162*)g_aHi;
        H[2*i]   = __floats2bfloat162_rn(v.x, v.y);
        H[2*i+1] = __floats2bfloat162_rn(v.z, v.w);
        return;
    }
    const float* in;
    __nv_bfloat16* obf = nullptr;
    __half* ohf = nullptr;
    int K, N, bx, by;
    if (b < 4096) {
        int w = b >> 10, l = b & 1023;
        bx = (l & 31) * 32; by = (l >> 5) * 32; K = DM; N = DM;
        in = (w == 0) ? wq : (w == 1) ? wk : (w == 2) ? wv : wo;
        obf = (w == 0) ? g_wqkvT : (w == 1) ? g_wqkvT + DM*DM
            : (w == 2) ? g_wqkvT + 2*DM*DM : g_woT;
    } else if (b < 8192) {
        int l = b - 4096;
        bx = (l & 127) * 32; by = (l >> 7) * 32; K = DM; N = DFF;
        in = w1; ohf = g_w1T;
    } else {
        int l = b - 8192;
        bx = (l & 31) * 32; by = (l >> 5) * 32; K = DFF; N = DM;
        in = w2; ohf = g_w2T;
    }
    const int tx = threadIdx.x & 31, ty = threadIdx.x >> 5;
    #pragma unroll
    for (int i = 0; i < 4; i++)
        t[ty + i*8][tx] = in[(size_t)(by + ty + i*8) * N + bx + tx];
    __syncthreads();
    #pragma unroll
    for (int i = 0; i < 4; i++) {
        float v = t[tx][ty + i*8];
        size_t oi = (size_t)(bx + ty + i*8) * K + by + tx;
        if (obf) obf[oi] = __float2bfloat16(v);
        else     ohf[oi] = __float2half_rn(v);
    }
}

// ---------------------------------------------------------------------------
// LayerNorm; SPLIT variant also emits fp16 of the normalized output
// ---------------------------------------------------------------------------
template<int SPLIT>
__global__ void __launch_bounds__(256) ln_kernel(
    const float* __restrict__ in, const float* __restrict__ g,
    const float* __restrict__ b, float* __restrict__ out,
    __half* __restrict__ oHi)
{
    __shared__ float red[8];
    __shared__ float s_mean, s_rstd;
    const int row = blockIdx.x;
    const int tid = threadIdx.x;
    const float* x = in + (size_t)row * DM;

    float v[4];
    float s = 0.f;
    #pragma unroll
    for (int i = 0; i < 4; i++) { v[i] = x[tid + i*256]; s += v[i]; }
    #pragma unroll
    for (int o = 16; o; o >>= 1) s += __shfl_xor_sync(0xffffffffu, s, o);
    if ((tid & 31) == 0) red[tid >> 5] = s;
    __syncthreads();
    if (tid == 0) {
        float t = 0.f;
        #pragma unroll
        for (int i = 0; i < 8; i++) t += red[i];
        s_mean = t * (1.f / DM);
    }
    __syncthreads();
    const float mean = s_mean;

    s = 0.f;
    #pragma unroll
    for (int i = 0; i < 4; i++) { float d = v[i] - mean; s += d * d; }
    #pragma unroll
    for (int o = 16; o; o >>= 1) s += __shfl_xor_sync(0xffffffffu, s, o);
    if ((tid & 31) == 0) red[tid >> 5] = s;
    __syncthreads();
    if (tid == 0) {
        float t = 0.f;
        #pragma unroll
        for (int i = 0; i < 8; i++) t += red[i];
        s_rstd = rsqrtf(t * (1.f / DM) + 1e-5f);
    }
    __syncthreads();
    const float rstd = s_rstd;

    float* orow = out + (size_t)row * DM;
    #pragma unroll
    for (int i = 0; i < 4; i++) {
        int c = tid + i*256;
        float y = (v[i] - mean) * rstd * g[c] + b[c];
        orow[c] = y;
        if (SPLIT)
            oHi[(size_t)row * DM + c] = __float2half_rn(y);
    }
}

// ---------------------------------------------------------------------------
// Launch
// ---------------------------------------------------------------------------
extern "C" void kernel_launch(void* const* d_in, const int* in_sizes, int n_in,
                              void* d_out, int out_size)
{
    const float* data = (const float*)d_in[0];
    const float* wq   = (const float*)d_in[2];
    const float* bq   = (const float*)d_in[3];
    const float* wk   = (const float*)d_in[4];
    const float* bk   = (const float*)d_in[5];
    const float* wv   = (const float*)d_in[6];
    const float* bv   = (const float*)d_in[7];
    const float* wo   = (const float*)d_in[8];
    const float* bo   = (const float*)d_in[9];
    const float* ln1g = (const float*)d_in[10];
    const float* ln1b = (const float*)d_in[11];
    const float* w1   = (const float*)d_in[12];
    const float* b1   = (const float*)d_in[13];
    const float* w2   = (const float*)d_in[14];
    const float* b2   = (const float*)d_in[15];
    const float* ln2g = (const float*)d_in[16];
    const float* ln2b = (const float*)d_in[17];
    float* out = (float*)d_out;

    float *x, *t;
    __nv_bfloat16 *aHi, *qHi, *kHi, *vHi, *cHi, *wqkvT, *woT;
    __half *xHi, *hHi, *w1T, *w2T;
    cudaGetSymbolAddress((void**)&x,   g_x);
    cudaGetSymbolAddress((void**)&t,   g_t);
    cudaGetSymbolAddress((void**)&aHi, g_aHi);
    cudaGetSymbolAddress((void**)&xHi, g_xHi);
    cudaGetSymbolAddress((void**)&hHi, g_hHi);
    cudaGetSymbolAddress((void**)&qHi, g_qHi);
    cudaGetSymbolAddress((void**)&kHi, g_kHi);
    cudaGetSymbolAddress((void**)&vHi, g_vHi);
    cudaGetSymbolAddress((void**)&cHi, g_ctxHi);
    cudaGetSymbolAddress((void**)&wqkvT, g_wqkvT);
    cudaGetSymbolAddress((void**)&woT, g_woT);
    cudaGetSymbolAddress((void**)&w1T, g_w1T);
    cudaGetSymbolAddress((void**)&w2T, g_w2T);

    cudaFuncSetAttribute(attn_mma,
                         cudaFuncAttributeMaxDynamicSharedMemorySize, ATT_SMEM);
    cudaFuncSetAttribute(gemm1<0>,
                         cudaFuncAttributeMaxDynamicSharedMemorySize, GEMM1_SMEM);
    cudaFuncSetAttribute(gemm1<1>,
                         cudaFuncAttributeMaxDynamicSharedMemorySize, GEMM1_SMEM);
    cudaFuncSetAttribute(gemmh<1>,
                         cudaFuncAttributeMaxDynamicSharedMemorySize, GEMM1_SMEM);
    cudaFuncSetAttribute(gemmh<2>,
                         cudaFuncAttributeMaxDynamicSharedMemorySize, GEMM1_SMEM);

    // 0: weight transposes + data convert
    transpose_all<<<16384, 256>>>(wq, wk, wv, wo, w1, w2, data);

    // 1: QKV (1-term bf16)
    gemm1<0><<<dim3(3*DM/128, MTOT/128), 128, GEMM1_SMEM>>>(
        aHi, wqkvT, bq, bk, bv, nullptr, nullptr, DM, DM);

    // 2: attention
    attn_mma<<<dim3(SEQ/128, BSZ*NH), 256, ATT_SMEM>>>(qHi, kHi, vHi, cHi);

    // 3: Wo + residual ; 4: LN1 (+fp16)
    gemm1<1><<<dim3(DM/128, MTOT/128), 128, GEMM1_SMEM>>>(
        cHi, woT, bo, nullptr, nullptr, data, t, DM, DM);
    ln_kernel<1><<<MTOT, 256>>>(t, ln1g, ln1b, x, xHi);

    // 5: FFN1 (relu + fp16 out)
    gemmh<2><<<dim3(DFF/128, MTOT/128), 128, GEMM1_SMEM>>>(
        xHi, w1T, b1, nullptr, nullptr, hHi, DM, DFF);

    // 6: FFN2 + residual ; 7: LN2 -> out
    gemmh<1><<<dim3(DM/128, MTOT/128), 128, GEMM1_SMEM>>>(
        hHi, w2T, b2, x, t, nullptr, DFF, DM);
    ln_kernel<0><<<MTOT, 256>>>(t, ln2g, ln2b, out, nullptr);
}

// round 15
// speedup vs baseline: 1.0519x; 1.0519x over previous
#include <cuda_runtime.h>
#include <cuda_bf16.h>
#include <cuda_fp16.h>
#include <stdint.h>
#include <math.h>

// Problem constants
#define BSZ 2
#define SEQ 2048
#define DM  1024
#define DFF 4096
#define NH  16
#define DKV 64
#define MTOT (BSZ*SEQ)   // 4096

// ---------------------------------------------------------------------------
// Scratch buffers
// ---------------------------------------------------------------------------
__device__ __align__(256) float g_x  [MTOT*DM];
__device__ __align__(256) float g_t  [MTOT*DM];

__device__ __align__(256) __nv_bfloat16 g_aHi[MTOT*DM];
__device__ __align__(256) __half g_xHi[MTOT*DM];
__device__ __align__(256) __half g_hHi[(size_t)MTOT*DFF];
__device__ __align__(256) __nv_bfloat16 g_qHi[MTOT*DM];
__device__ __align__(256) __nv_bfloat16 g_kHi[MTOT*DM];
__device__ __align__(256) __nv_bfloat16 g_vHi[MTOT*DM];
__device__ __align__(256) __nv_bfloat16 g_ctxHi[MTOT*DM];
__device__ __align__(256) __nv_bfloat16 g_wqkvT[3*DM*DM];
__device__ __align__(256) __nv_bfloat16 g_woT[DM*DM];
__device__ __align__(256) __half g_w1T[(size_t)DFF*DM];
__device__ __align__(256) __half g_w2T[(size_t)DM*DFF];

// ---------------------------------------------------------------------------
// PTX helpers
// ---------------------------------------------------------------------------
static __device__ __forceinline__ uint32_t smem_u32(const void* p) {
    uint32_t a;
    asm("{ .reg .u64 t; cvta.to.shared.u64 t, %1; cvt.u32.u64 %0, t; }"
        : "=r"(a) : "l"(p));
    return a;
}
static __device__ __forceinline__ void cp16(uint32_t dst, const void* src) {
    asm volatile("cp.async.cg.shared.global [%0], [%1], 16;" :: "r"(dst), "l"(src));
}
static __device__ __forceinline__ uint32_t swz(uint32_t off) {
    return off ^ ((off >> 3) & 0x70);
}
static __device__ __forceinline__ void ldsm4(uint32_t* r, uint32_t addr) {
    asm volatile("ldmatrix.sync.aligned.m8n8.x4.shared.b16 {%0,%1,%2,%3}, [%4];"
        : "=r"(r[0]), "=r"(r[1]), "=r"(r[2]), "=r"(r[3]) : "r"(addr));
}
static __device__ __forceinline__ void ldsm4t(uint32_t* r, uint32_t addr) {
    asm volatile("ldmatrix.sync.aligned.m8n8.x4.trans.shared.b16 {%0,%1,%2,%3}, [%4];"
        : "=r"(r[0]), "=r"(r[1]), "=r"(r[2]), "=r"(r[3]) : "r"(addr));
}
static __device__ __forceinline__ void hmma(float* d, const uint32_t* a,
                                            const uint32_t* b) {
    asm volatile(
        "mma.sync.aligned.m16n8k16.row.col.f32.bf16.bf16.f32 "
        "{%0,%1,%2,%3}, {%4,%5,%6,%7}, {%8,%9}, {%0,%1,%2,%3};"
        : "+f"(d[0]), "+f"(d[1]), "+f"(d[2]), "+f"(d[3])
        : "r"(a[0]), "r"(a[1]), "r"(a[2]), "r"(a[3]), "r"(b[0]), "r"(b[1]));
}
static __device__ __forceinline__ void hmmah(float* d, const uint32_t* a,
                                             const uint32_t* b) {
    asm volatile(
        "mma.sync.aligned.m16n8k16.row.col.f32.f16.f16.f32 "
        "{%0,%1,%2,%3}, {%4,%5,%6,%7}, {%8,%9}, {%0,%1,%2,%3};"
        : "+f"(d[0]), "+f"(d[1]), "+f"(d[2]), "+f"(d[3])
        : "r"(a[0]), "r"(a[1]), "r"(a[2]), "r"(a[3]), "r"(b[0]), "r"(b[1]));
}
static __device__ __forceinline__ uint32_t packbf2(float x, float y) {
    __nv_bfloat162 t = __floats2bfloat162_rn(x, y);
    return *reinterpret_cast<uint32_t*>(&t);
}
static __device__ __forceinline__ uint32_t packh2(float x, float y) {
    __half2 t = __floats2half2_rn(x, y);
    return *reinterpret_cast<uint32_t*>(&t);
}

// ===========================================================================
// 1-TERM GEMM, 4-warp CTA: 128x128 tile, warp grid 2Mx2N, warp tile 64x64.
// (R13-proven version: NO fragment double-buffering — reg ceiling is binding.)
// 64 KB smem -> 2 CTAs/SM.
// bf16 variant (QKV/Wo): MODE 0 QKV epilogue (q scaled by log2e/8), MODE 1
// fp32+residual.
// ===========================================================================
#define G1_STAGE (32*1024)
#define G1_OFF_B (16*1024)
#define GEMM1_SMEM (2*G1_STAGE)   // 64 KB
#define QSCALE 0.1803368801111244f   // log2(e) / 8

static __device__ __forceinline__ void load_tile1(
    uint32_t sb, int stage, int it,
    const __nv_bfloat16* __restrict__ A, const __nv_bfloat16* __restrict__ B,
    int mBase, int nBase, int K, int tid)
{
    const uint32_t base = sb + stage * G1_STAGE;
    const int k0 = it * 64;
    #pragma unroll
    for (int i = 0; i < 8; i++) {
        int c = tid + i * 128;
        int row = c >> 3, chk = c & 7;
        cp16(base + swz(row * 128 + chk * 16),
             A + (size_t)(mBase + row) * K + k0 + chk * 8);
    }
    #pragma unroll
    for (int i = 0; i < 8; i++) {
        int c = tid + i * 128;
        int row = c >> 3, chk = c & 7;
        cp16(base + G1_OFF_B + swz(row * 128 + chk * 16),
             B + (size_t)(nBase + row) * K + k0 + chk * 8);
    }
    asm volatile("cp.async.commit_group;" ::: "memory");
}

template<int MODE>
__global__ void __launch_bounds__(128, 2) gemm1(
    const __nv_bfloat16* __restrict__ A, const __nv_bfloat16* __restrict__ B,
    const float* __restrict__ b0, const float* __restrict__ b1,
    const float* __restrict__ b2, const float* __restrict__ res,
    float* __restrict__ o0, int K, int ldc)
{
    extern __shared__ char smem[];
    const uint32_t sb = smem_u32(smem);
    const int tid  = threadIdx.x;
    const int wid  = tid >> 5;
    const int lane = tid & 31;
    const int warpM = wid >> 1;
    const int warpN = wid & 1;
    const int mBase = blockIdx.y * 128;
    const int nBase = blockIdx.x * 128;

    float acc[4][8][4];
    #pragma unroll
    for (int i = 0; i < 4; i++)
        #pragma unroll
        for (int j = 0; j < 8; j++)
            #pragma unroll
            for (int e = 0; e < 4; e++) acc[i][j][e] = 0.f;

    const int T = K / 64;
    load_tile1(sb, 0, 0, A, B, mBase, nBase, K, tid);

    const int aRow  = warpM * 64 + ((lane >> 3) & 1) * 8 + (lane & 7);
    const int aKsel = (lane >> 4) * 16;
    const int bRow  = warpN * 64 + (lane >> 4) * 8 + (lane & 7);
    const int bKsel = ((lane >> 3) & 1) * 16;

    for (int it = 0; it < T; it++) {
        const int s = it & 1;
        if (it + 1 < T) {
            load_tile1(sb, s ^ 1, it + 1, A, B, mBase, nBase, K, tid);
            asm volatile("cp.async.wait_group 1;" ::: "memory");
        } else {
            asm volatile("cp.async.wait_group 0;" ::: "memory");
        }
        __syncthreads();

        const uint32_t st = sb + s * G1_STAGE;
        #pragma unroll
        for (int ks = 0; ks < 4; ks++) {
            const int kb = ks * 32;
            uint32_t a[4][4], b[4][4];
            #pragma unroll
            for (int ma = 0; ma < 4; ma++)
                ldsm4(a[ma], st + swz((uint32_t)(aRow + ma * 16) * 128 + kb + aKsel));
            #pragma unroll
            for (int np = 0; np < 4; np++)
                ldsm4(b[np], st + G1_OFF_B +
                      swz((uint32_t)(bRow + np * 16) * 128 + kb + bKsel));
            #pragma unroll
            for (int ma = 0; ma < 4; ma++)
                #pragma unroll
                for (int na = 0; na < 8; na++)
                    hmma(acc[ma][na], a[ma], &b[na >> 1][(na & 1) * 2]);
        }
        __syncthreads();
    }

    const int gr = lane >> 2;
    const int gc = (lane & 3) * 2;
    #pragma unroll
    for (int ma = 0; ma < 4; ma++) {
        #pragma unroll
        for (int na = 0; na < 8; na++) {
            const int row0 = mBase + warpM * 64 + ma * 16 + gr;
            const int colg = nBase + warpN * 64 + na * 8 + gc;
            float d0 = acc[ma][na][0], d1 = acc[ma][na][1];
            float d2 = acc[ma][na][2], d3 = acc[ma][na][3];
            if (MODE == 0) {    // QKV (q pre-scaled by log2e/8 for exp2 softmax)
                const int seg = colg >> 10;
                const int col = colg & 1023;
                const float* bb = (seg == 0) ? b0 : ((seg == 1) ? b1 : b2);
                __nv_bfloat16* Hi = (seg == 0) ? g_qHi : ((seg == 1) ? g_kHi : g_vHi);
                const float sc = (seg == 0) ? QSCALE : 1.0f;
                float bv0 = bb[col], bv1 = bb[col + 1];
                size_t gi0 = (size_t)row0 * 1024 + col;
                size_t gi1 = (size_t)(row0 + 8) * 1024 + col;
                *(uint32_t*)(Hi + gi0) = packbf2((d0 + bv0) * sc, (d1 + bv1) * sc);
                *(uint32_t*)(Hi + gi1) = packbf2((d2 + bv0) * sc, (d3 + bv1) * sc);
            } else {            // fp32 + residual
                float bv0 = b0[colg], bv1 = b0[colg + 1];
                size_t gi0 = (size_t)row0 * ldc + colg;
                size_t gi1 = (size_t)(row0 + 8) * ldc + colg;
                float2 r0 = *(const float2*)(res + gi0);
                float2 r1 = *(const float2*)(res + gi1);
                *(float2*)(o0 + gi0) = make_float2(d0 + bv0 + r0.x, d1 + bv1 + r0.y);
                *(float2*)(o0 + gi1) = make_float2(d2 + bv0 + r1.x, d3 + bv1 + r1.y);
            }
        }
    }
}

// ===========================================================================
// fp16 variant (FFN), R13-proven structure.
// MODE 1: fp32 out + residual   MODE 2: relu + fp16 out
// ===========================================================================
static __device__ __forceinline__ void load_tileh(
    uint32_t sb, int stage, int it,
    const __half* __restrict__ A, const __half* __restrict__ B,
    int mBase, int nBase, int K, int tid)
{
    const uint32_t base = sb + stage * G1_STAGE;
    const int k0 = it * 64;
    #pragma unroll
    for (int i = 0; i < 8; i++) {
        int c = tid + i * 128;
        int row = c >> 3, chk = c & 7;
        cp16(base + swz(row * 128 + chk * 16),
             A + (size_t)(mBase + row) * K + k0 + chk * 8);
    }
    #pragma unroll
    for (int i = 0; i < 8; i++) {
        int c = tid + i * 128;
        int row = c >> 3, chk = c & 7;
        cp16(base + G1_OFF_B + swz(row * 128 + chk * 16),
             B + (size_t)(nBase + row) * K + k0 + chk * 8);
    }
    asm volatile("cp.async.commit_group;" ::: "memory");
}

template<int MODE>
__global__ void __launch_bounds__(128, 2) gemmh(
    const __half* __restrict__ A, const __half* __restrict__ B,
    const float* __restrict__ b0, const float* __restrict__ res,
    float* __restrict__ o0, __half* __restrict__ oH,
    int K, int ldc)
{
    extern __shared__ char smem[];
    const uint32_t sb = smem_u32(smem);
    const int tid  = threadIdx.x;
    const int wid  = tid >> 5;
    const int lane = tid & 31;
    const int warpM = wid >> 1;
    const int warpN = wid & 1;
    const int mBase = blockIdx.y * 128;
    const int nBase = blockIdx.x * 128;

    float acc[4][8][4];
    #pragma unroll
    for (int i = 0; i < 4; i++)
        #pragma unroll
        for (int j = 0; j < 8; j++)
            #pragma unroll
            for (int e = 0; e < 4; e++) acc[i][j][e] = 0.f;

    const int T = K / 64;
    load_tileh(sb, 0, 0, A, B, mBase, nBase, K, tid);

    const int aRow  = warpM * 64 + ((lane >> 3) & 1) * 8 + (lane & 7);
    const int aKsel = (lane >> 4) * 16;
    const int bRow  = warpN * 64 + (lane >> 4) * 8 + (lane & 7);
    const int bKsel = ((lane >> 3) & 1) * 16;

    for (int it = 0; it < T; it++) {
        const int s = it & 1;
        if (it + 1 < T) {
            load_tileh(sb, s ^ 1, it + 1, A, B, mBase, nBase, K, tid);
            asm volatile("cp.async.wait_group 1;" ::: "memory");
        } else {
            asm volatile("cp.async.wait_group 0;" ::: "memory");
        }
        __syncthreads();

        const uint32_t st = sb + s * G1_STAGE;
        #pragma unroll
        for (int ks = 0; ks < 4; ks++) {
            const int kb = ks * 32;
            uint32_t a[4][4], b[4][4];
            #pragma unroll
            for (int ma = 0; ma < 4; ma++)
                ldsm4(a[ma], st + swz((uint32_t)(aRow + ma * 16) * 128 + kb + aKsel));
            #pragma unroll
            for (int np = 0; np < 4; np++)
                ldsm4(b[np], st + G1_OFF_B +
                      swz((uint32_t)(bRow + np * 16) * 128 + kb + bKsel));
            #pragma unroll
            for (int ma = 0; ma < 4; ma++)
                #pragma unroll
                for (int na = 0; na < 8; na++)
                    hmmah(acc[ma][na], a[ma], &b[na >> 1][(na & 1) * 2]);
        }
        __syncthreads();
    }

    const int gr = lane >> 2;
    const int gc = (lane & 3) * 2;
    #pragma unroll
    for (int ma = 0; ma < 4; ma++) {
        #pragma unroll
        for (int na = 0; na < 8; na++) {
            const int row0 = mBase + warpM * 64 + ma * 16 + gr;
            const int colg = nBase + warpN * 64 + na * 8 + gc;
            float d0 = acc[ma][na][0], d1 = acc[ma][na][1];
            float d2 = acc[ma][na][2], d3 = acc[ma][na][3];
            float bv0 = b0[colg], bv1 = b0[colg + 1];
            size_t gi0 = (size_t)row0 * ldc + colg;
            size_t gi1 = (size_t)(row0 + 8) * ldc + colg;
            if (MODE == 1) {
                float2 r0 = *(const float2*)(res + gi0);
                float2 r1 = *(const float2*)(res + gi1);
                *(float2*)(o0 + gi0) = make_float2(d0 + bv0 + r0.x, d1 + bv1 + r0.y);
                *(float2*)(o0 + gi1) = make_float2(d2 + bv0 + r1.x, d3 + bv1 + r1.y);
            } else {
                *(uint32_t*)(oH + gi0) = packh2(fmaxf(d0 + bv0, 0.f),
                                                fmaxf(d1 + bv1, 0.f));
                *(uint32_t*)(oH + gi1) = packh2(fmaxf(d2 + bv0, 0.f),
                                                fmaxf(d3 + bv1, 0.f));
            }
        }
    }
}

// ---------------------------------------------------------------------------
// Flash attention: 1-term bf16, no-max softmax with exp2 (log2e folded into
// the Q scale at the QKV epilogue — removes one FMUL per score element).
// 80 KB smem -> 2 CTAs/SM.
// ---------------------------------------------------------------------------
#define AQ_HI 0
#define AKV   (16*1024)
#define AKV_STAGE (32*1024)
#define ATT_SMEM (AKV + 2*AKV_STAGE)   // 80 KB

__global__ void __launch_bounds__(256, 2) attn_mma(
    const __nv_bfloat16* __restrict__ Qhi,
    const __nv_bfloat16* __restrict__ Khi,
    const __nv_bfloat16* __restrict__ Vhi,
    __nv_bfloat16* __restrict__ ctxHi)
{
    extern __shared__ char smem[];
    const uint32_t sb = smem_u32(smem);
    const int tid  = threadIdx.x;
    const int wid  = tid >> 5;
    const int lane = tid & 31;
    const int bh = blockIdx.y;
    const size_t base  = (size_t)bh * (SEQ * DKV);
    const size_t qbase = base + (size_t)blockIdx.x * 128 * DKV;

    #pragma unroll
    for (int i = 0; i < 4; i++) {
        int c = tid + i * 256;
        int row = c >> 3, chk = c & 7;
        cp16(sb + AQ_HI + swz(row * 128 + chk * 16),
             Qhi + qbase + (size_t)row * 64 + chk * 8);
    }
    auto load_kv = [&](int stage, int it) {
        const uint32_t dstb = sb + AKV + stage * AKV_STAGE;
        const int kt = it * 128;
        #pragma unroll
        for (int i = 0; i < 8; i++) {
            int c = tid + i * 256;
            int buf = c >> 10;
            int idx = c & 1023;
            int row = idx >> 3, chk = idx & 7;
            const __nv_bfloat16* src = buf ? Vhi : Khi;
            cp16(dstb + buf * 16384 + swz(row * 128 + chk * 16),
                 src + base + (size_t)(kt + row) * 64 + chk * 8);
        }
        asm volatile("cp.async.commit_group;" ::: "memory");
    };
    load_kv(0, 0);

    float rsum0 = 0.f, rsum1 = 0.f;
    float o[8][4];
    #pragma unroll
    for (int n = 0; n < 8; n++)
        #pragma unroll
        for (int e = 0; e < 4; e++) o[n][e] = 0.f;

    const int aRow  = wid * 16 + ((lane >> 3) & 1) * 8 + (lane & 7);
    const int aKsel = (lane >> 4) * 16;
    const int bR    = (lane >> 4) * 8 + (lane & 7);
    const int bKsel = ((lane >> 3) & 1) * 16;
    const int vRowL = ((lane >> 3) & 1) * 8 + (lane & 7);
    const int vDL   = (lane >> 4) * 16;

    const int T = SEQ / 128;   // 16
    for (int it = 0; it < T; it++) {
        const int s = it & 1;
        if (it + 1 < T) {
            load_kv(s ^ 1, it + 1);
            asm volatile("cp.async.wait_group 1;" ::: "memory");
        } else {
            asm volatile("cp.async.wait_group 0;" ::: "memory");
        }
        __syncthreads();
        const uint32_t st = sb + AKV + s * AKV_STAGE;

        #pragma unroll
        for (int half = 0; half < 2; half++) {
            const uint32_t kOff = st + half * 8192;
            const uint32_t vOff = st + 16384 + half * 8192;

            float sacc[8][4];
            #pragma unroll
            for (int n = 0; n < 8; n++)
                #pragma unroll
                for (int e = 0; e < 4; e++) sacc[n][e] = 0.f;

            #pragma unroll
            for (int ks = 0; ks < 4; ks++) {
                const int kbyte = ks * 32;
                uint32_t qh[4];
                ldsm4(qh, sb + AQ_HI + swz((uint32_t)aRow * 128 + kbyte + aKsel));
                uint32_t kh[4][4];
                #pragma unroll
                for (int nb = 0; nb < 4; nb++)
                    ldsm4(kh[nb], kOff +
                          swz((uint32_t)(nb * 16 + bR) * 128 + kbyte + bKsel));
                #pragma unroll
                for (int nt = 0; nt < 8; nt++)
                    hmma(sacc[nt], qh, &kh[nt >> 1][(nt & 1) * 2]);
            }

            #pragma unroll
            for (int j = 0; j < 4; j++) {
                float* s0 = sacc[2*j];
                float* s1 = sacc[2*j + 1];
                float p00 = exp2f(s0[0]), p01 = exp2f(s0[1]);
                float p02 = exp2f(s0[2]), p03 = exp2f(s0[3]);
                float p10 = exp2f(s1[0]), p11 = exp2f(s1[1]);
                float p12 = exp2f(s1[2]), p13 = exp2f(s1[3]);
                rsum0 += p00 + p01 + p10 + p11;
                rsum1 += p02 + p03 + p12 + p13;
                uint32_t ph[4];
                ph[0] = packbf2(p00, p01);
                ph[1] = packbf2(p02, p03);
                ph[2] = packbf2(p10, p11);
                ph[3] = packbf2(p12, p13);
                uint32_t vh[4][4];
                #pragma unroll
                for (int dblk = 0; dblk < 4; dblk++)
                    ldsm4t(vh[dblk], vOff +
                           swz((uint32_t)(j * 16 + vRowL) * 128 +
                               dblk * 32 + vDL));
                #pragma unroll
                for (int dt = 0; dt < 8; dt++)
                    hmma(o[dt], ph, &vh[dt >> 1][(dt & 1) * 2]);
            }
        }
        __syncthreads();
    }

    rsum0 += __shfl_xor_sync(0xffffffffu, rsum0, 1);
    rsum0 += __shfl_xor_sync(0xffffffffu, rsum0, 2);
    rsum1 += __shfl_xor_sync(0xffffffffu, rsum1, 1);
    rsum1 += __shfl_xor_sync(0xffffffffu, rsum1, 2);

    const int b = bh >> 4, h = bh & 15;
    const float inv0 = 1.f / rsum0;
    const float inv1 = 1.f / rsum1;
    const int s2 = blockIdx.x * 128 + wid * 16 + (lane >> 2);
    #pragma unroll
    for (int nt = 0; nt < 8; nt++) {
        const int d0 = h * 64 + nt * 8 + (lane & 3) * 2;
        size_t gi0 = ((size_t)(b * SEQ + s2))     * DM + d0;
        size_t gi1 = ((size_t)(b * SEQ + s2 + 8)) * DM + d0;
        *(uint32_t*)(ctxHi + gi0) = packbf2(o[nt][0] * inv0, o[nt][1] * inv0);
        *(uint32_t*)(ctxHi + gi1) = packbf2(o[nt][2] * inv1, o[nt][3] * inv1);
    }
}

// ---------------------------------------------------------------------------
// Merged preprocessing: weight transposes + data fp32->bf16 convert
// ---------------------------------------------------------------------------
__global__ void __launch_bounds__(256) transpose_all(
    const float* __restrict__ wq, const float* __restrict__ wk,
    const float* __restrict__ wv, const float* __restrict__ wo,
    const float* __restrict__ w1, const float* __restrict__ w2,
    const float* __restrict__ data)
{
    __shared__ float t[32][33];
    const int b = blockIdx.x;
    if (b >= 12288) {
        int i = (b - 12288) * 256 + threadIdx.x;
        float4 v = ((const float4*)data)[i];
        __nv_bfloat162* H = (__nv_bfloat162*)g_aHi;
        H[2*i]   = __floats2bfloat162_rn(v.x, v.y);
        H[2*i+1] = __floats2bfloat162_rn(v.z, v.w);
        return;
    }
    const float* in;
    __nv_bfloat16* obf = nullptr;
    __half* ohf = nullptr;
    int K, N, bx, by;
    if (b < 4096) {
        int w = b >> 10, l = b & 1023;
        bx = (l & 31) * 32; by = (l >> 5) * 32; K = DM; N = DM;
        in = (w == 0) ? wq : (w == 1) ? wk : (w == 2) ? wv : wo;
        obf = (w == 0) ? g_wqkvT : (w == 1) ? g_wqkvT + DM*DM
            : (w == 2) ? g_wqkvT + 2*DM*DM : g_woT;
    } else if (b < 8192) {
        int l = b - 4096;
        bx = (l & 127) * 32; by = (l >> 7) * 32; K = DM; N = DFF;
        in = w1; ohf = g_w1T;
    } else {
        int l = b - 8192;
        bx = (l & 31) * 32; by = (l >> 5) * 32; K = DFF; N = DM;
        in = w2; ohf = g_w2T;
    }
    const int tx = threadIdx.x & 31, ty = threadIdx.x >> 5;
    #pragma unroll
    for (int i = 0; i < 4; i++)
        t[ty + i*8][tx] = in[(size_t)(by + ty + i*8) * N + bx + tx];
    __syncthreads();
    #pragma unroll
    for (int i = 0; i < 4; i++) {
        float v = t[tx][ty + i*8];
        size_t oi = (size_t)(bx + ty + i*8) * K + by + tx;
        if (obf) obf[oi] = __float2bfloat16(v);
        else     ohf[oi] = __float2half_rn(v);
    }
}

// ---------------------------------------------------------------------------
// LayerNorm; SPLIT variant also emits fp16 of the normalized output
// ---------------------------------------------------------------------------
template<int SPLIT>
__global__ void __launch_bounds__(256) ln_kernel(
    const float* __restrict__ in, const float* __restrict__ g,
    const float* __restrict__ b, float* __restrict__ out,
    __half* __restrict__ oHi)
{
    __shared__ float red[8];
    __shared__ float s_mean, s_rstd;
    const int row = blockIdx.x;
    const int tid = threadIdx.x;
    const float* x = in + (size_t)row * DM;

    float v[4];
    float s = 0.f;
    #pragma unroll
    for (int i = 0; i < 4; i++) { v[i] = x[tid + i*256]; s += v[i]; }
    #pragma unroll
    for (int o = 16; o; o >>= 1) s += __shfl_xor_sync(0xffffffffu, s, o);
    if ((tid & 31) == 0) red[tid >> 5] = s;
    __syncthreads();
    if (tid == 0) {
        float t = 0.f;
        #pragma unroll
        for (int i = 0; i < 8; i++) t += red[i];
        s_mean = t * (1.f / DM);
    }
    __syncthreads();
    const float mean = s_mean;

    s = 0.f;
    #pragma unroll
    for (int i = 0; i < 4; i++) { float d = v[i] - mean; s += d * d; }
    #pragma unroll
    for (int o = 16; o; o >>= 1) s += __shfl_xor_sync(0xffffffffu, s, o);
    if ((tid & 31) == 0) red[tid >> 5] = s;
    __syncthreads();
    if (tid == 0) {
        float t = 0.f;
        #pragma unroll
        for (int i = 0; i < 8; i++) t += red[i];
        s_rstd = rsqrtf(t * (1.f / DM) + 1e-5f);
    }
    __syncthreads();
    const float rstd = s_rstd;

    float* orow = out + (size_t)row * DM;
    #pragma unroll
    for (int i = 0; i < 4; i++) {
        int c = tid + i*256;
        float y = (v[i] - mean) * rstd * g[c] + b[c];
        orow[c] = y;
        if (SPLIT)
            oHi[(size_t)row * DM + c] = __float2half_rn(y);
    }
}

// ---------------------------------------------------------------------------
// Launch
// ---------------------------------------------------------------------------
extern "C" void kernel_launch(void* const* d_in, const int* in_sizes, int n_in,
                              void* d_out, int out_size)
{
    const float* data = (const float*)d_in[0];
    const float* wq   = (const float*)d_in[2];
    const float* bq   = (const float*)d_in[3];
    const float* wk   = (const float*)d_in[4];
    const float* bk   = (const float*)d_in[5];
    const float* wv   = (const float*)d_in[6];
    const float* bv   = (const float*)d_in[7];
    const float* wo   = (const float*)d_in[8];
    const float* bo   = (const float*)d_in[9];
    const float* ln1g = (const float*)d_in[10];
    const float* ln1b = (const float*)d_in[11];
    const float* w1   = (const float*)d_in[12];
    const float* b1   = (const float*)d_in[13];
    const float* w2   = (const float*)d_in[14];
    const float* b2   = (const float*)d_in[15];
    const float* ln2g = (const float*)d_in[16];
    const float* ln2b = (const float*)d_in[17];
    float* out = (float*)d_out;

    float *x, *t;
    __nv_bfloat16 *aHi, *qHi, *kHi, *vHi, *cHi, *wqkvT, *woT;
    __half *xHi, *hHi, *w1T, *w2T;
    cudaGetSymbolAddress((void**)&x,   g_x);
    cudaGetSymbolAddress((void**)&t,   g_t);
    cudaGetSymbolAddress((void**)&aHi, g_aHi);
    cudaGetSymbolAddress((void**)&xHi, g_xHi);
    cudaGetSymbolAddress((void**)&hHi, g_hHi);
    cudaGetSymbolAddress((void**)&qHi, g_qHi);
    cudaGetSymbolAddress((void**)&kHi, g_kHi);
    cudaGetSymbolAddress((void**)&vHi, g_vHi);
    cudaGetSymbolAddress((void**)&cHi, g_ctxHi);
    cudaGetSymbolAddress((void**)&wqkvT, g_wqkvT);
    cudaGetSymbolAddress((void**)&woT, g_woT);
    cudaGetSymbolAddress((void**)&w1T, g_w1T);
    cudaGetSymbolAddress((void**)&w2T, g_w2T);

    cudaFuncSetAttribute(attn_mma,
                         cudaFuncAttributeMaxDynamicSharedMemorySize, ATT_SMEM);
    cudaFuncSetAttribute(gemm1<0>,
                         cudaFuncAttributeMaxDynamicSharedMemorySize, GEMM1_SMEM);
    cudaFuncSetAttribute(gemm1<1>,
                         cudaFuncAttributeMaxDynamicSharedMemorySize, GEMM1_SMEM);
    cudaFuncSetAttribute(gemmh<1>,
                         cudaFuncAttributeMaxDynamicSharedMemorySize, GEMM1_SMEM);
    cudaFuncSetAttribute(gemmh<2>,
                         cudaFuncAttributeMaxDynamicSharedMemorySize, GEMM1_SMEM);

    // 0: weight transposes + data convert
    transpose_all<<<16384, 256>>>(wq, wk, wv, wo, w1, w2, data);

    // 1: QKV (1-term bf16, q pre-scaled by log2e/8)
    gemm1<0><<<dim3(3*DM/128, MTOT/128), 128, GEMM1_SMEM>>>(
        aHi, wqkvT, bq, bk, bv, nullptr, nullptr, DM, DM);

    // 2: attention (exp2 softmax)
    attn_mma<<<dim3(SEQ/128, BSZ*NH), 256, ATT_SMEM>>>(qHi, kHi, vHi, cHi);

    // 3: Wo + residual ; 4: LN1 (+fp16)
    gemm1<1><<<dim3(DM/128, MTOT/128), 128, GEMM1_SMEM>>>(
        cHi, woT, bo, nullptr, nullptr, data, t, DM, DM);
    ln_kernel<1><<<MTOT, 256>>>(t, ln1g, ln1b, x, xHi);

    // 5: FFN1 (relu + fp16 out)
    gemmh<2><<<dim3(DFF/128, MTOT/128), 128, GEMM1_SMEM>>>(
        xHi, w1T, b1, nullptr, nullptr, hHi, DM, DFF);

    // 6: FFN2 + residual ; 7: LN2 -> out
    gemmh<1><<<dim3(DM/128, MTOT/128), 128, GEMM1_SMEM>>>(
        hHi, w2T, b2, x, t, nullptr, DFF, DM);
    ln_kernel<0><<<MTOT, 256>>>(t, ln2g, ln2b, out, nullptr);
}

// round 16
// speedup vs baseline: 1.0938x; 1.0398x over previous
#include <cuda_runtime.h>
#include <cuda_bf16.h>
#include <cuda_fp16.h>
#include <stdint.h>
#include <math.h>

// Problem constants
#define BSZ 2
#define SEQ 2048
#define DM  1024
#define DFF 4096
#define NH  16
#define DKV 64
#define MTOT (BSZ*SEQ)   // 4096

// ---------------------------------------------------------------------------
// Scratch buffers
// ---------------------------------------------------------------------------
__device__ __align__(256) float g_x  [MTOT*DM];
__device__ __align__(256) float g_t  [MTOT*DM];

__device__ __align__(256) __nv_bfloat16 g_aHi[MTOT*DM];
__device__ __align__(256) __half g_xHi[MTOT*DM];
__device__ __align__(256) __half g_hHi[(size_t)MTOT*DFF];
__device__ __align__(256) __nv_bfloat16 g_qHi[MTOT*DM];
__device__ __align__(256) __nv_bfloat16 g_kHi[MTOT*DM];
__device__ __align__(256) __nv_bfloat16 g_vHi[MTOT*DM];
__device__ __align__(256) __nv_bfloat16 g_ctxHi[MTOT*DM];
__device__ __align__(256) __nv_bfloat16 g_wqkvT[3*DM*DM];
__device__ __align__(256) __nv_bfloat16 g_woT[DM*DM];
__device__ __align__(256) __half g_w1T[(size_t)DFF*DM];
__device__ __align__(256) __half g_w2T[(size_t)DM*DFF];

// ---------------------------------------------------------------------------
// PTX helpers
// ---------------------------------------------------------------------------
static __device__ __forceinline__ uint32_t smem_u32(const void* p) {
    uint32_t a;
    asm("{ .reg .u64 t; cvta.to.shared.u64 t, %1; cvt.u32.u64 %0, t; }"
        : "=r"(a) : "l"(p));
    return a;
}
static __device__ __forceinline__ void cp16(uint32_t dst, const void* src) {
    asm volatile("cp.async.cg.shared.global [%0], [%1], 16;" :: "r"(dst), "l"(src));
}
static __device__ __forceinline__ uint32_t swz(uint32_t off) {
    return off ^ ((off >> 3) & 0x70);
}
static __device__ __forceinline__ void ldsm4(uint32_t* r, uint32_t addr) {
    asm volatile("ldmatrix.sync.aligned.m8n8.x4.shared.b16 {%0,%1,%2,%3}, [%4];"
        : "=r"(r[0]), "=r"(r[1]), "=r"(r[2]), "=r"(r[3]) : "r"(addr));
}
static __device__ __forceinline__ void ldsm4t(uint32_t* r, uint32_t addr) {
    asm volatile("ldmatrix.sync.aligned.m8n8.x4.trans.shared.b16 {%0,%1,%2,%3}, [%4];"
        : "=r"(r[0]), "=r"(r[1]), "=r"(r[2]), "=r"(r[3]) : "r"(addr));
}
static __device__ __forceinline__ void hmma(float* d, const uint32_t* a,
                                            const uint32_t* b) {
    asm volatile(
        "mma.sync.aligned.m16n8k16.row.col.f32.bf16.bf16.f32 "
        "{%0,%1,%2,%3}, {%4,%5,%6,%7}, {%8,%9}, {%0,%1,%2,%3};"
        : "+f"(d[0]), "+f"(d[1]), "+f"(d[2]), "+f"(d[3])
        : "r"(a[0]), "r"(a[1]), "r"(a[2]), "r"(a[3]), "r"(b[0]), "r"(b[1]));
}
static __device__ __forceinline__ void hmmah(float* d, const uint32_t* a,
                                             const uint32_t* b) {
    asm volatile(
        "mma.sync.aligned.m16n8k16.row.col.f32.f16.f16.f32 "
        "{%0,%1,%2,%3}, {%4,%5,%6,%7}, {%8,%9}, {%0,%1,%2,%3};"
        : "+f"(d[0]), "+f"(d[1]), "+f"(d[2]), "+f"(d[3])
        : "r"(a[0]), "r"(a[1]), "r"(a[2]), "r"(a[3]), "r"(b[0]), "r"(b[1]));
}
static __device__ __forceinline__ uint32_t packbf2(float x, float y) {
    __nv_bfloat162 t = __floats2bfloat162_rn(x, y);
    return *reinterpret_cast<uint32_t*>(&t);
}
static __device__ __forceinline__ uint32_t packh2(float x, float y) {
    __half2 t = __floats2half2_rn(x, y);
    return *reinterpret_cast<uint32_t*>(&t);
}

// ===========================================================================
// 1-TERM GEMM, 4-warp CTA: 128x128 tile, warp 64x64 (R13/R15-proven).
// 64 KB smem -> 2 CTAs/SM.
// bf16 variant: MODE 0 QKV epilogue (q scaled log2e/8), MODE 1 fp32+residual
// ===========================================================================
#define G1_STAGE (32*1024)
#define G1_OFF_B (16*1024)
#define GEMM1_SMEM (2*G1_STAGE)   // 64 KB
#define QSCALE 0.1803368801111244f   // log2(e) / 8

static __device__ __forceinline__ void load_tile1(
    uint32_t sb, int stage, int it,
    const __nv_bfloat16* __restrict__ A, const __nv_bfloat16* __restrict__ B,
    int mBase, int nBase, int K, int tid)
{
    const uint32_t base = sb + stage * G1_STAGE;
    const int k0 = it * 64;
    #pragma unroll
    for (int i = 0; i < 8; i++) {
        int c = tid + i * 128;
        int row = c >> 3, chk = c & 7;
        cp16(base + swz(row * 128 + chk * 16),
             A + (size_t)(mBase + row) * K + k0 + chk * 8);
    }
    #pragma unroll
    for (int i = 0; i < 8; i++) {
        int c = tid + i * 128;
        int row = c >> 3, chk = c & 7;
        cp16(base + G1_OFF_B + swz(row * 128 + chk * 16),
             B + (size_t)(nBase + row) * K + k0 + chk * 8);
    }
    asm volatile("cp.async.commit_group;" ::: "memory");
}

template<int MODE>
__global__ void __launch_bounds__(128, 2) gemm1(
    const __nv_bfloat16* __restrict__ A, const __nv_bfloat16* __restrict__ B,
    const float* __restrict__ b0, const float* __restrict__ b1,
    const float* __restrict__ b2, const float* __restrict__ res,
    float* __restrict__ o0, int K, int ldc)
{
    extern __shared__ char smem[];
    const uint32_t sb = smem_u32(smem);
    const int tid  = threadIdx.x;
    const int wid  = tid >> 5;
    const int lane = tid & 31;
    const int warpM = wid >> 1;
    const int warpN = wid & 1;
    const int mBase = blockIdx.y * 128;
    const int nBase = blockIdx.x * 128;

    float acc[4][8][4];
    #pragma unroll
    for (int i = 0; i < 4; i++)
        #pragma unroll
        for (int j = 0; j < 8; j++)
            #pragma unroll
            for (int e = 0; e < 4; e++) acc[i][j][e] = 0.f;

    const int T = K / 64;
    load_tile1(sb, 0, 0, A, B, mBase, nBase, K, tid);

    const int aRow  = warpM * 64 + ((lane >> 3) & 1) * 8 + (lane & 7);
    const int aKsel = (lane >> 4) * 16;
    const int bRow  = warpN * 64 + (lane >> 4) * 8 + (lane & 7);
    const int bKsel = ((lane >> 3) & 1) * 16;

    for (int it = 0; it < T; it++) {
        const int s = it & 1;
        if (it + 1 < T) {
            load_tile1(sb, s ^ 1, it + 1, A, B, mBase, nBase, K, tid);
            asm volatile("cp.async.wait_group 1;" ::: "memory");
        } else {
            asm volatile("cp.async.wait_group 0;" ::: "memory");
        }
        __syncthreads();

        const uint32_t st = sb + s * G1_STAGE;
        #pragma unroll
        for (int ks = 0; ks < 4; ks++) {
            const int kb = ks * 32;
            uint32_t a[4][4], b[4][4];
            #pragma unroll
            for (int ma = 0; ma < 4; ma++)
                ldsm4(a[ma], st + swz((uint32_t)(aRow + ma * 16) * 128 + kb + aKsel));
            #pragma unroll
            for (int np = 0; np < 4; np++)
                ldsm4(b[np], st + G1_OFF_B +
                      swz((uint32_t)(bRow + np * 16) * 128 + kb + bKsel));
            #pragma unroll
            for (int ma = 0; ma < 4; ma++)
                #pragma unroll
                for (int na = 0; na < 8; na++)
                    hmma(acc[ma][na], a[ma], &b[na >> 1][(na & 1) * 2]);
        }
        __syncthreads();
    }

    const int gr = lane >> 2;
    const int gc = (lane & 3) * 2;
    #pragma unroll
    for (int ma = 0; ma < 4; ma++) {
        #pragma unroll
        for (int na = 0; na < 8; na++) {
            const int row0 = mBase + warpM * 64 + ma * 16 + gr;
            const int colg = nBase + warpN * 64 + na * 8 + gc;
            float d0 = acc[ma][na][0], d1 = acc[ma][na][1];
            float d2 = acc[ma][na][2], d3 = acc[ma][na][3];
            if (MODE == 0) {    // QKV (q pre-scaled by log2e/8 for exp2 softmax)
                const int seg = colg >> 10;
                const int col = colg & 1023;
                const float* bb = (seg == 0) ? b0 : ((seg == 1) ? b1 : b2);
                __nv_bfloat16* Hi = (seg == 0) ? g_qHi : ((seg == 1) ? g_kHi : g_vHi);
                const float sc = (seg == 0) ? QSCALE : 1.0f;
                float bv0 = bb[col], bv1 = bb[col + 1];
                size_t gi0 = (size_t)row0 * 1024 + col;
                size_t gi1 = (size_t)(row0 + 8) * 1024 + col;
                *(uint32_t*)(Hi + gi0) = packbf2((d0 + bv0) * sc, (d1 + bv1) * sc);
                *(uint32_t*)(Hi + gi1) = packbf2((d2 + bv0) * sc, (d3 + bv1) * sc);
            } else {            // fp32 + residual
                float bv0 = b0[colg], bv1 = b0[colg + 1];
                size_t gi0 = (size_t)row0 * ldc + colg;
                size_t gi1 = (size_t)(row0 + 8) * ldc + colg;
                float2 r0 = *(const float2*)(res + gi0);
                float2 r1 = *(const float2*)(res + gi1);
                *(float2*)(o0 + gi0) = make_float2(d0 + bv0 + r0.x, d1 + bv1 + r0.y);
                *(float2*)(o0 + gi1) = make_float2(d2 + bv0 + r1.x, d3 + bv1 + r1.y);
            }
        }
    }
}

// ===========================================================================
// fp16 variant (FFN), R13/R15-proven structure.
// MODE 1: fp32 out + residual   MODE 2: relu + fp16 out
// ===========================================================================
static __device__ __forceinline__ void load_tileh(
    uint32_t sb, int stage, int it,
    const __half* __restrict__ A, const __half* __restrict__ B,
    int mBase, int nBase, int K, int tid)
{
    const uint32_t base = sb + stage * G1_STAGE;
    const int k0 = it * 64;
    #pragma unroll
    for (int i = 0; i < 8; i++) {
        int c = tid + i * 128;
        int row = c >> 3, chk = c & 7;
        cp16(base + swz(row * 128 + chk * 16),
             A + (size_t)(mBase + row) * K + k0 + chk * 8);
    }
    #pragma unroll
    for (int i = 0; i < 8; i++) {
        int c = tid + i * 128;
        int row = c >> 3, chk = c & 7;
        cp16(base + G1_OFF_B + swz(row * 128 + chk * 16),
             B + (size_t)(nBase + row) * K + k0 + chk * 8);
    }
    asm volatile("cp.async.commit_group;" ::: "memory");
}

template<int MODE>
__global__ void __launch_bounds__(128, 2) gemmh(
    const __half* __restrict__ A, const __half* __restrict__ B,
    const float* __restrict__ b0, const float* __restrict__ res,
    float* __restrict__ o0, __half* __restrict__ oH,
    int K, int ldc)
{
    extern __shared__ char smem[];
    const uint32_t sb = smem_u32(smem);
    const int tid  = threadIdx.x;
    const int wid  = tid >> 5;
    const int lane = tid & 31;
    const int warpM = wid >> 1;
    const int warpN = wid & 1;
    const int mBase = blockIdx.y * 128;
    const int nBase = blockIdx.x * 128;

    float acc[4][8][4];
    #pragma unroll
    for (int i = 0; i < 4; i++)
        #pragma unroll
        for (int j = 0; j < 8; j++)
            #pragma unroll
            for (int e = 0; e < 4; e++) acc[i][j][e] = 0.f;

    const int T = K / 64;
    load_tileh(sb, 0, 0, A, B, mBase, nBase, K, tid);

    const int aRow  = warpM * 64 + ((lane >> 3) & 1) * 8 + (lane & 7);
    const int aKsel = (lane >> 4) * 16;
    const int bRow  = warpN * 64 + (lane >> 4) * 8 + (lane & 7);
    const int bKsel = ((lane >> 3) & 1) * 16;

    for (int it = 0; it < T; it++) {
        const int s = it & 1;
        if (it + 1 < T) {
            load_tileh(sb, s ^ 1, it + 1, A, B, mBase, nBase, K, tid);
            asm volatile("cp.async.wait_group 1;" ::: "memory");
        } else {
            asm volatile("cp.async.wait_group 0;" ::: "memory");
        }
        __syncthreads();

        const uint32_t st = sb + s * G1_STAGE;
        #pragma unroll
        for (int ks = 0; ks < 4; ks++) {
            const int kb = ks * 32;
            uint32_t a[4][4], b[4][4];
            #pragma unroll
            for (int ma = 0; ma < 4; ma++)
                ldsm4(a[ma], st + swz((uint32_t)(aRow + ma * 16) * 128 + kb + aKsel));
            #pragma unroll
            for (int np = 0; np < 4; np++)
                ldsm4(b[np], st + G1_OFF_B +
                      swz((uint32_t)(bRow + np * 16) * 128 + kb + bKsel));
            #pragma unroll
            for (int ma = 0; ma < 4; ma++)
                #pragma unroll
                for (int na = 0; na < 8; na++)
                    hmmah(acc[ma][na], a[ma], &b[na >> 1][(na & 1) * 2]);
        }
        __syncthreads();
    }

    const int gr = lane >> 2;
    const int gc = (lane & 3) * 2;
    #pragma unroll
    for (int ma = 0; ma < 4; ma++) {
        #pragma unroll
        for (int na = 0; na < 8; na++) {
            const int row0 = mBase + warpM * 64 + ma * 16 + gr;
            const int colg = nBase + warpN * 64 + na * 8 + gc;
            float d0 = acc[ma][na][0], d1 = acc[ma][na][1];
            float d2 = acc[ma][na][2], d3 = acc[ma][na][3];
            float bv0 = b0[colg], bv1 = b0[colg + 1];
            size_t gi0 = (size_t)row0 * ldc + colg;
            size_t gi1 = (size_t)(row0 + 8) * ldc + colg;
            if (MODE == 1) {
                float2 r0 = *(const float2*)(res + gi0);
                float2 r1 = *(const float2*)(res + gi1);
                *(float2*)(o0 + gi0) = make_float2(d0 + bv0 + r0.x, d1 + bv1 + r0.y);
                *(float2*)(o0 + gi1) = make_float2(d2 + bv0 + r1.x, d3 + bv1 + r1.y);
            } else {
                *(uint32_t*)(oH + gi0) = packh2(fmaxf(d0 + bv0, 0.f),
                                                fmaxf(d1 + bv1, 0.f));
                *(uint32_t*)(oH + gi1) = packh2(fmaxf(d2 + bv0, 0.f),
                                                fmaxf(d3 + bv1, 0.f));
            }
        }
    }
}

// ---------------------------------------------------------------------------
// Flash attention: 1-term bf16, no-max exp2 softmax.
// NEW: 4 warps x 32 q-rows (2 m-tiles/warp) — halves K/V fragment re-reads
// (smem crossbar was the binding resource). V frags shared across m-tiles.
// 128 threads, 80 KB smem, ~200 regs -> 2 CTAs/SM.
// ---------------------------------------------------------------------------
#define AQ_HI 0
#define AKV   (16*1024)
#define AKV_STAGE (32*1024)
#define ATT_SMEM (AKV + 2*AKV_STAGE)   // 80 KB

__global__ void __launch_bounds__(128, 2) attn_mma(
    const __nv_bfloat16* __restrict__ Qhi,
    const __nv_bfloat16* __restrict__ Khi,
    const __nv_bfloat16* __restrict__ Vhi,
    __nv_bfloat16* __restrict__ ctxHi)
{
    extern __shared__ char smem[];
    const uint32_t sb = smem_u32(smem);
    const int tid  = threadIdx.x;
    const int wid  = tid >> 5;
    const int lane = tid & 31;
    const int bh = blockIdx.y;
    const size_t base  = (size_t)bh * (SEQ * DKV);
    const size_t qbase = base + (size_t)blockIdx.x * 128 * DKV;

    // Q tile (128 x 64 bf16 = 16 KB), 128 threads
    #pragma unroll
    for (int i = 0; i < 8; i++) {
        int c = tid + i * 128;
        int row = c >> 3, chk = c & 7;
        cp16(sb + AQ_HI + swz(row * 128 + chk * 16),
             Qhi + qbase + (size_t)row * 64 + chk * 8);
    }
    auto load_kv = [&](int stage, int it) {     // 128 keys: K 16KB | V 16KB
        const uint32_t dstb = sb + AKV + stage * AKV_STAGE;
        const int kt = it * 128;
        #pragma unroll
        for (int i = 0; i < 16; i++) {
            int c = tid + i * 128;
            int buf = c >> 10;
            int idx = c & 1023;
            int row = idx >> 3, chk = idx & 7;
            const __nv_bfloat16* src = buf ? Vhi : Khi;
            cp16(dstb + buf * 16384 + swz(row * 128 + chk * 16),
                 src + base + (size_t)(kt + row) * 64 + chk * 8);
        }
        asm volatile("cp.async.commit_group;" ::: "memory");
    };
    load_kv(0, 0);

    float rsum[2][2] = {{0.f, 0.f}, {0.f, 0.f}};
    float o[2][8][4];
    #pragma unroll
    for (int ma = 0; ma < 2; ma++)
        #pragma unroll
        for (int n = 0; n < 8; n++)
            #pragma unroll
            for (int e = 0; e < 4; e++) o[ma][n][e] = 0.f;

    const int aRowL = ((lane >> 3) & 1) * 8 + (lane & 7);
    const int aKsel = (lane >> 4) * 16;
    const int bR    = (lane >> 4) * 8 + (lane & 7);
    const int bKsel = ((lane >> 3) & 1) * 16;
    const int vRowL = ((lane >> 3) & 1) * 8 + (lane & 7);
    const int vDL   = (lane >> 4) * 16;
    const int qBaseRow = wid * 32;

    const int T = SEQ / 128;   // 16
    for (int it = 0; it < T; it++) {
        const int s = it & 1;
        if (it + 1 < T) {
            load_kv(s ^ 1, it + 1);
            asm volatile("cp.async.wait_group 1;" ::: "memory");
        } else {
            asm volatile("cp.async.wait_group 0;" ::: "memory");
        }
        __syncthreads();
        const uint32_t st = sb + AKV + s * AKV_STAGE;

        #pragma unroll
        for (int half = 0; half < 2; half++) {
            const uint32_t kOff = st + half * 8192;
            const uint32_t vOff = st + 16384 + half * 8192;

            // S = q @ k^T for 32 q-rows x 64 keys
            float sacc[2][8][4];
            #pragma unroll
            for (int ma = 0; ma < 2; ma++)
                #pragma unroll
                for (int n = 0; n < 8; n++)
                    #pragma unroll
                    for (int e = 0; e < 4; e++) sacc[ma][n][e] = 0.f;

            #pragma unroll
            for (int ks = 0; ks < 4; ks++) {
                const int kbyte = ks * 32;
                uint32_t qh[2][4];
                #pragma unroll
                for (int ma = 0; ma < 2; ma++)
                    ldsm4(qh[ma], sb + AQ_HI +
                          swz((uint32_t)(qBaseRow + ma * 16 + aRowL) * 128 +
                              kbyte + aKsel));
                uint32_t kh[4][4];
                #pragma unroll
                for (int nb = 0; nb < 4; nb++)
                    ldsm4(kh[nb], kOff +
                          swz((uint32_t)(nb * 16 + bR) * 128 + kbyte + bKsel));
                #pragma unroll
                for (int ma = 0; ma < 2; ma++)
                    #pragma unroll
                    for (int nt = 0; nt < 8; nt++)
                        hmma(sacc[ma][nt], qh[ma], &kh[nt >> 1][(nt & 1) * 2]);
            }

            // Softmax + PV per 16-key chunk; V frags shared across m-tiles
            #pragma unroll
            for (int j = 0; j < 4; j++) {
                uint32_t vh[4][4];
                #pragma unroll
                for (int dblk = 0; dblk < 4; dblk++)
                    ldsm4t(vh[dblk], vOff +
                           swz((uint32_t)(j * 16 + vRowL) * 128 +
                               dblk * 32 + vDL));
                #pragma unroll
                for (int ma = 0; ma < 2; ma++) {
                    float* s0 = sacc[ma][2*j];
                    float* s1 = sacc[ma][2*j + 1];
                    float p00 = exp2f(s0[0]), p01 = exp2f(s0[1]);
                    float p02 = exp2f(s0[2]), p03 = exp2f(s0[3]);
                    float p10 = exp2f(s1[0]), p11 = exp2f(s1[1]);
                    float p12 = exp2f(s1[2]), p13 = exp2f(s1[3]);
                    rsum[ma][0] += p00 + p01 + p10 + p11;
                    rsum[ma][1] += p02 + p03 + p12 + p13;
                    uint32_t ph[4];
                    ph[0] = packbf2(p00, p01);
                    ph[1] = packbf2(p02, p03);
                    ph[2] = packbf2(p10, p11);
                    ph[3] = packbf2(p12, p13);
                    #pragma unroll
                    for (int dt = 0; dt < 8; dt++)
                        hmma(o[ma][dt], ph, &vh[dt >> 1][(dt & 1) * 2]);
                }
            }
        }
        __syncthreads();
    }

    // Deferred l-reductions + epilogue
    const int b = bh >> 4, h = bh & 15;
    #pragma unroll
    for (int ma = 0; ma < 2; ma++) {
        float r0 = rsum[ma][0], r1 = rsum[ma][1];
        r0 += __shfl_xor_sync(0xffffffffu, r0, 1);
        r0 += __shfl_xor_sync(0xffffffffu, r0, 2);
        r1 += __shfl_xor_sync(0xffffffffu, r1, 1);
        r1 += __shfl_xor_sync(0xffffffffu, r1, 2);
        const float inv0 = 1.f / r0;
        const float inv1 = 1.f / r1;
        const int s2 = blockIdx.x * 128 + qBaseRow + ma * 16 + (lane >> 2);
        #pragma unroll
        for (int nt = 0; nt < 8; nt++) {
            const int d0 = h * 64 + nt * 8 + (lane & 3) * 2;
            size_t gi0 = ((size_t)(b * SEQ + s2))     * DM + d0;
            size_t gi1 = ((size_t)(b * SEQ + s2 + 8)) * DM + d0;
            *(uint32_t*)(ctxHi + gi0) = packbf2(o[ma][nt][0] * inv0,
                                                o[ma][nt][1] * inv0);
            *(uint32_t*)(ctxHi + gi1) = packbf2(o[ma][nt][2] * inv1,
                                                o[ma][nt][3] * inv1);
        }
    }
}

// ---------------------------------------------------------------------------
// Merged preprocessing: weight transposes + data fp32->bf16 convert
// ---------------------------------------------------------------------------
__global__ void __launch_bounds__(256) transpose_all(
    const float* __restrict__ wq, const float* __restrict__ wk,
    const float* __restrict__ wv, const float* __restrict__ wo,
    const float* __restrict__ w1, const float* __restrict__ w2,
    const float* __restrict__ data)
{
    __shared__ float t[32][33];
    const int b = blockIdx.x;
    if (b >= 12288) {
        int i = (b - 12288) * 256 + threadIdx.x;
        float4 v = ((const float4*)data)[i];
        __nv_bfloat162* H = (__nv_bfloat162*)g_aHi;
        H[2*i]   = __floats2bfloat162_rn(v.x, v.y);
        H[2*i+1] = __floats2bfloat162_rn(v.z, v.w);
        return;
    }
    const float* in;
    __nv_bfloat16* obf = nullptr;
    __half* ohf = nullptr;
    int K, N, bx, by;
    if (b < 4096) {
        int w = b >> 10, l = b & 1023;
        bx = (l & 31) * 32; by = (l >> 5) * 32; K = DM; N = DM;
        in = (w == 0) ? wq : (w == 1) ? wk : (w == 2) ? wv : wo;
        obf = (w == 0) ? g_wqkvT : (w == 1) ? g_wqkvT + DM*DM
            : (w == 2) ? g_wqkvT + 2*DM*DM : g_woT;
    } else if (b < 8192) {
        int l = b - 4096;
        bx = (l & 127) * 32; by = (l >> 7) * 32; K = DM; N = DFF;
        in = w1; ohf = g_w1T;
    } else {
        int l = b - 8192;
        bx = (l & 31) * 32; by = (l >> 5) * 32; K = DFF; N = DM;
        in = w2; ohf = g_w2T;
    }
    const int tx = threadIdx.x & 31, ty = threadIdx.x >> 5;
    #pragma unroll
    for (int i = 0; i < 4; i++)
        t[ty + i*8][tx] = in[(size_t)(by + ty + i*8) * N + bx + tx];
    __syncthreads();
    #pragma unroll
    for (int i = 0; i < 4; i++) {
        float v = t[tx][ty + i*8];
        size_t oi = (size_t)(bx + ty + i*8) * K + by + tx;
        if (obf) obf[oi] = __float2bfloat16(v);
        else     ohf[oi] = __float2half_rn(v);
    }
}

// ---------------------------------------------------------------------------
// LayerNorm; SPLIT variant also emits fp16 of the normalized output
// ---------------------------------------------------------------------------
template<int SPLIT>
__global__ void __launch_bounds__(256) ln_kernel(
    const float* __restrict__ in, const float* __restrict__ g,
    const float* __restrict__ b, float* __restrict__ out,
    __half* __restrict__ oHi)
{
    __shared__ float red[8];
    __shared__ float s_mean, s_rstd;
    const int row = blockIdx.x;
    const int tid = threadIdx.x;
    const float* x = in + (size_t)row * DM;

    float v[4];
    float s = 0.f;
    #pragma unroll
    for (int i = 0; i < 4; i++) { v[i] = x[tid + i*256]; s += v[i]; }
    #pragma unroll
    for (int o = 16; o; o >>= 1) s += __shfl_xor_sync(0xffffffffu, s, o);
    if ((tid & 31) == 0) red[tid >> 5] = s;
    __syncthreads();
    if (tid == 0) {
        float t = 0.f;
        #pragma unroll
        for (int i = 0; i < 8; i++) t += red[i];
        s_mean = t * (1.f / DM);
    }
    __syncthreads();
    const float mean = s_mean;

    s = 0.f;
    #pragma unroll
    for (int i = 0; i < 4; i++) { float d = v[i] - mean; s += d * d; }
    #pragma unroll
    for (int o = 16; o; o >>= 1) s += __shfl_xor_sync(0xffffffffu, s, o);
    if ((tid & 31) == 0) red[tid >> 5] = s;
    __syncthreads();
    if (tid == 0) {
        float t = 0.f;
        #pragma unroll
        for (int i = 0; i < 8; i++) t += red[i];
        s_rstd = rsqrtf(t * (1.f / DM) + 1e-5f);
    }
    __syncthreads();
    const float rstd = s_rstd;

    float* orow = out + (size_t)row * DM;
    #pragma unroll
    for (int i = 0; i < 4; i++) {
        int c = tid + i*256;
        float y = (v[i] - mean) * rstd * g[c] + b[c];
        orow[c] = y;
        if (SPLIT)
            oHi[(size_t)row * DM + c] = __float2half_rn(y);
    }
}

// ---------------------------------------------------------------------------
// Launch
// ---------------------------------------------------------------------------
extern "C" void kernel_launch(void* const* d_in, const int* in_sizes, int n_in,
                              void* d_out, int out_size)
{
    const float* data = (const float*)d_in[0];
    const float* wq   = (const float*)d_in[2];
    const float* bq   = (const float*)d_in[3];
    const float* wk   = (const float*)d_in[4];
    const float* bk   = (const float*)d_in[5];
    const float* wv   = (const float*)d_in[6];
    const float* bv   = (const float*)d_in[7];
    const float* wo   = (const float*)d_in[8];
    const float* bo   = (const float*)d_in[9];
    const float* ln1g = (const float*)d_in[10];
    const float* ln1b = (const float*)d_in[11];
    const float* w1   = (const float*)d_in[12];
    const float* b1   = (const float*)d_in[13];
    const float* w2   = (const float*)d_in[14];
    const float* b2   = (const float*)d_in[15];
    const float* ln2g = (const float*)d_in[16];
    const float* ln2b = (const float*)d_in[17];
    float* out = (float*)d_out;

    float *x, *t;
    __nv_bfloat16 *aHi, *qHi, *kHi, *vHi, *cHi, *wqkvT, *woT;
    __half *xHi, *hHi, *w1T, *w2T;
    cudaGetSymbolAddress((void**)&x,   g_x);
    cudaGetSymbolAddress((void**)&t,   g_t);
    cudaGetSymbolAddress((void**)&aHi, g_aHi);
    cudaGetSymbolAddress((void**)&xHi, g_xHi);
    cudaGetSymbolAddress((void**)&hHi, g_hHi);
    cudaGetSymbolAddress((void**)&qHi, g_qHi);
    cudaGetSymbolAddress((void**)&kHi, g_kHi);
    cudaGetSymbolAddress((void**)&vHi, g_vHi);
    cudaGetSymbolAddress((void**)&cHi, g_ctxHi);
    cudaGetSymbolAddress((void**)&wqkvT, g_wqkvT);
    cudaGetSymbolAddress((void**)&woT, g_woT);
    cudaGetSymbolAddress((void**)&w1T, g_w1T);
    cudaGetSymbolAddress((void**)&w2T, g_w2T);

    cudaFuncSetAttribute(attn_mma,
                         cudaFuncAttributeMaxDynamicSharedMemorySize, ATT_SMEM);
    cudaFuncSetAttribute(gemm1<0>,
                         cudaFuncAttributeMaxDynamicSharedMemorySize, GEMM1_SMEM);
    cudaFuncSetAttribute(gemm1<1>,
                         cudaFuncAttributeMaxDynamicSharedMemorySize, GEMM1_SMEM);
    cudaFuncSetAttribute(gemmh<1>,
                         cudaFuncAttributeMaxDynamicSharedMemorySize, GEMM1_SMEM);
    cudaFuncSetAttribute(gemmh<2>,
                         cudaFuncAttributeMaxDynamicSharedMemorySize, GEMM1_SMEM);

    // 0: weight transposes + data convert
    transpose_all<<<16384, 256>>>(wq, wk, wv, wo, w1, w2, data);

    // 1: QKV (1-term bf16, q pre-scaled by log2e/8)
    gemm1<0><<<dim3(3*DM/128, MTOT/128), 128, GEMM1_SMEM>>>(
        aHi, wqkvT, bq, bk, bv, nullptr, nullptr, DM, DM);

    // 2: attention (exp2 softmax, 4-warp wide-tile)
    attn_mma<<<dim3(SEQ/128, BSZ*NH), 128, ATT_SMEM>>>(qHi, kHi, vHi, cHi);

    // 3: Wo + residual ; 4: LN1 (+fp16)
    gemm1<1><<<dim3(DM/128, MTOT/128), 128, GEMM1_SMEM>>>(
        cHi, woT, bo, nullptr, nullptr, data, t, DM, DM);
    ln_kernel<1><<<MTOT, 256>>>(t, ln1g, ln1b, x, xHi);

    // 5: FFN1 (relu + fp16 out)
    gemmh<2><<<dim3(DFF/128, MTOT/128), 128, GEMM1_SMEM>>>(
        xHi, w1T, b1, nullptr, nullptr, hHi, DM, DFF);

    // 6: FFN2 + residual ; 7: LN2 -> out
    gemmh<1><<<dim3(DM/128, MTOT/128), 128, GEMM1_SMEM>>>(
        hHi, w2T, b2, x, t, nullptr, DFF, DM);
    ln_kernel<0><<<MTOT, 256>>>(t, ln2g, ln2b, out, nullptr);
}